// round 13
// baseline (speedup 1.0000x reference)
#include <cuda_runtime.h>
#include <cuda_bf16.h>
#include <math.h>
#include <stdint.h>

// ---------------- problem constants ----------------
#define TOTN   131072      // B*N nodes
#define EMAX   1048576
#define FDIM   64
#define HSD    128
#define RSD    32
#define NPG    4096        // nodes per graph (temporal length)
#define SCB    512         // scan blocks
#define SCCH   (TOTN / SCB)

typedef __nv_bfloat16 bf16;

// ---------------- device scratch (no cudaMalloc allowed) ----------------
__device__ int   g_is64;
__device__ float g_dinv [TOTN];
__device__ int   g_cnt  [TOTN];
__device__ int   g_rowp [TOTN + 1];
__device__ int   g_curs [TOTN];
__device__ int   g_adj  [EMAX];
__device__ int   g_part [SCB];
// bf16 hi/lo planes for activations
__device__ __align__(16) bf16 g_A1h[TOTN * FDIM], g_A1l[TOTN * FDIM];
__device__ __align__(16) bf16 g_H1h[TOTN * HSD],  g_H1l[TOTN * HSD];
__device__ __align__(16) bf16 g_A3h[TOTN * RSD],  g_A3l[TOTN * RSD];
__device__ __align__(16) bf16 g_H3h[TOTN * HSD],  g_H3l[TOTN * HSD];
__device__ __align__(16) bf16 g_C1h[TOTN * HSD],  g_C1l[TOTN * HSD];
__device__ __align__(16) bf16 g_C2h[TOTN * RSD],  g_C2l[TOTN * RSD];
// fp32 intermediates
__device__ float g_H2raw[TOTN * RSD];
__device__ float g_H2   [TOTN * RSD];
// weight planes (k-major [tap][COUT][CIN])
__device__ __align__(16) bf16 g_W1h[128 * 64],      g_W1l[128 * 64];
__device__ __align__(16) bf16 g_W2h[32 * 128],      g_W2l[32 * 128];
__device__ __align__(16) bf16 g_W3h[128 * 32],      g_W3l[128 * 32];
__device__ __align__(16) bf16 g_T1h[3 * 128 * 128], g_T1l[3 * 128 * 128];
__device__ __align__(16) bf16 g_T2h[3 * 32 * 128],  g_T2l[3 * 32 * 128];
__device__ __align__(16) bf16 g_T3h[3 * 128 * 32],  g_T3l[3 * 128 * 32];

__device__ __forceinline__ uint32_t pack_bf(float a, float b) {
    __nv_bfloat162 t;
    t.x = __float2bfloat16(a);
    t.y = __float2bfloat16(b);
    return *reinterpret_cast<uint32_t*>(&t);
}
__device__ __forceinline__ uint32_t smem_u32(const void* p) {
    uint32_t a;
    asm("{ .reg .u64 t; cvta.to.shared.u64 t, %1; cvt.u32.u64 %0, t; }" : "=r"(a) : "l"(p));
    return a;
}
__device__ __forceinline__ void mma16816(float* d, uint32_t a0, uint32_t a1, uint32_t a2,
                                         uint32_t a3, uint32_t b0, uint32_t b1) {
    asm volatile(
        "mma.sync.aligned.m16n8k16.row.col.f32.bf16.bf16.f32 "
        "{%0,%1,%2,%3}, {%4,%5,%6,%7}, {%8,%9}, {%0,%1,%2,%3};"
        : "+f"(d[0]), "+f"(d[1]), "+f"(d[2]), "+f"(d[3])
        : "r"(a0), "r"(a1), "r"(a2), "r"(a3), "r"(b0), "r"(b1));
}
__device__ __forceinline__ void ldsm4(uint32_t& r0, uint32_t& r1, uint32_t& r2, uint32_t& r3,
                                      uint32_t addr) {
    asm volatile("ldmatrix.sync.aligned.m8n8.x4.shared.b16 {%0,%1,%2,%3}, [%4];"
                 : "=r"(r0), "=r"(r1), "=r"(r2), "=r"(r3) : "r"(addr));
}
__device__ __forceinline__ void cp16(uint32_t s, const void* g, bool p) {
    asm volatile("cp.async.cg.shared.global [%0], [%1], 16, %2;"
                 :: "r"(s), "l"(g), "r"(p ? 16 : 0));
}
#define CP_COMMIT() asm volatile("cp.async.commit_group;" ::: "memory")
#define CP_WAIT0()  asm volatile("cp.async.wait_group 0;" ::: "memory")

// ---------------- weight plane precompute ----------------
__device__ void wlin(const float* W, bf16* WH, bf16* WL, int CIN, int COUT, int tid, int nt) {
    for (int i = tid; i < CIN * COUT; i += nt) {
        int n = i / CIN, k = i % CIN;
        float w = W[(size_t)k * COUT + n];
        bf16 h = __float2bfloat16(w);
        WH[i] = h;
        WL[i] = __float2bfloat16(w - __bfloat162float(h));
    }
}
__device__ void wconv(const float* W, bf16* WH, bf16* WL, int CIN, int COUT, int tid, int nt) {
    for (int i = tid; i < 3 * CIN * COUT; i += nt) {
        int s = i / (CIN * COUT);
        int n = (i / CIN) % COUT;
        int k = i % CIN;
        float w = W[((size_t)n * CIN + k) * 3 + s];
        bf16 h = __float2bfloat16(w);
        WH[i] = h;
        WL[i] = __float2bfloat16(w - __bfloat162float(h));
    }
}
__global__ void prep_kernel(int* cnt, int n, const unsigned int* e,
                            const float* W1, const float* W2, const float* W3,
                            const float* T1, const float* T2, const float* T3) {
    int tid = blockIdx.x * blockDim.x + threadIdx.x;
    int nt  = gridDim.x * blockDim.x;
    for (int i = tid; i < n; i += nt) cnt[i] = 0;
    if (tid == 0) {
        int ok = 1;
        #pragma unroll 1
        for (int k = 0; k < 64; k++)
            if (e[2 * k + 1] != 0u) { ok = 0; break; }
        g_is64 = ok;
    }
    wlin(W1, g_W1h, g_W1l, 64, 128, tid, nt);
    wlin(W2, g_W2h, g_W2l, 128, 32, tid, nt);
    wlin(W3, g_W3h, g_W3l, 32, 128, tid, nt);
    wconv(T1, g_T1h, g_T1l, 128, 128, tid, nt);
    wconv(T2, g_T2h, g_T2l, 128, 32, tid, nt);
    wconv(T3, g_T3h, g_T3l, 32, 128, tid, nt);
}

// =========== unified dense layer on tensor cores ===========
template <int CIN, int COUT, int TAPS, int KCH, int HASBIAS, int HASRELU,
          int OUTPLANES, int HEADS, int TILES, int PIPE>
__global__ void __launch_bounds__(256, 2)
mma_layer(const bf16* __restrict__ XH, const bf16* __restrict__ XL,
          const bf16* __restrict__ WH, const bf16* __restrict__ WL,
          const float* __restrict__ bias,
          float* __restrict__ OUT, bf16* __restrict__ OH, bf16* __restrict__ OL,
          const float* __restrict__ HWpi, const float* __restrict__ HWn,
          const float* __restrict__ HWp, const float* __restrict__ Hbpi,
          const float* __restrict__ Hbn, const float* __restrict__ Hbp,
          float* __restrict__ hout) {
    constexpr int NCHC = CIN / KCH;
    constexpr int P    = KCH + 8;
    constexpr int HALO = (TAPS == 3) ? 1 : 0;
    constexpr int RSTG = 128 + 2 * HALO;
    constexpr bool BIG = (COUT == 128);
    constexpr bool ALLTAPS = (TAPS == 3) && (COUT == 32 || CIN == 32);
    constexpr bool BDB = (TAPS == 3) && !ALLTAPS && !PIPE;   // B double-buffer (conv1)
    constexpr int BTAPS = ALLTAPS ? 3 : 1;
    constexpr int U4   = KCH / 8;
    constexpr int FD   = BIG ? 2 : 1;
    constexpr int TD   = BIG ? 8 : 4;
    constexpr int NBUF = PIPE ? 2 : 1;
    constexpr int ABUFB  = RSTG * P * 2;
    constexpr int OFF_B  = NBUF * 2 * ABUFB;
    constexpr int BPL    = BTAPS * COUT * P * 2;
    constexpr int NBB    = BDB ? 2 : 1;
    constexpr int OFF_HB = OFF_B + NBB * 2 * BPL;

    extern __shared__ __align__(16) char smem[];
    const uint32_t sb = smem_u32(smem);
    float* hbuf = (float*)(smem + OFF_HB);

    int tid  = threadIdx.x;
    int w    = tid >> 5;
    int lane = tid & 31;
    int gid  = lane >> 2;
    int qid  = lane & 3;
    int seg  = lane >> 3;
    int rin  = lane & 7;
    int wm   = BIG ? (w & 3) : w;
    int wn   = BIG ? (w >> 2) : 0;

    float d[FD][TD][4];

    auto reset_acc = [&]() {
        #pragma unroll
        for (int f = 0; f < FD; f++)
            #pragma unroll
            for (int t = 0; t < TD; t++)
                #pragma unroll
                for (int i = 0; i < 4; i++) d[f][t][i] = 0.0f;
    };

    auto stage_A = [&](int trow0, int c0, int b) {
        int gbl = (trow0 / NPG) * NPG;
        uint32_t dh = sb + (uint32_t)(b * 2) * ABUFB;
        uint32_t dl = dh + ABUFB;
        for (int idx = tid; idx < RSTG * U4; idx += 256) {
            int r = idx / U4, j = (idx % U4) * 8;
            long src = (long)trow0 - HALO + r;
            bool ok = (!HALO) || (src >= gbl && src < (long)gbl + NPG);
            long sc = ok ? src : (long)trow0;
            cp16(dh + (uint32_t)(r * P + j) * 2, XH + sc * CIN + c0 + j, ok);
            cp16(dl + (uint32_t)(r * P + j) * 2, XL + sc * CIN + c0 + j, ok);
        }
    };
    auto stage_B_all = [&](int c0) {
        for (int idx = tid; idx < BTAPS * COUT * U4; idx += 256) {
            int n2 = idx / U4, j = (idx % U4) * 8;
            cp16(sb + OFF_B       + (uint32_t)(n2 * P + j) * 2, WH + (size_t)n2 * CIN + c0 + j, true);
            cp16(sb + OFF_B + BPL + (uint32_t)(n2 * P + j) * 2, WL + (size_t)n2 * CIN + c0 + j, true);
        }
    };
    auto stage_B_tap = [&](int s, int c0, int bb) {
        uint32_t bh = sb + OFF_B + (uint32_t)bb * 2 * BPL;
        for (int idx = tid; idx < COUT * U4; idx += 256) {
            int n = idx / U4, j = (idx % U4) * 8;
            cp16(bh       + (uint32_t)(n * P + j) * 2, WH + ((size_t)s * COUT + n) * CIN + c0 + j, true);
            cp16(bh + BPL + (uint32_t)(n * P + j) * 2, WL + ((size_t)s * COUT + n) * CIN + c0 + j, true);
        }
    };

    auto mma_chunk = [&](uint32_t aH, uint32_t aL, int s, int bt, int bb) {
        uint32_t bH = sb + OFF_B + (uint32_t)bb * 2 * BPL;
        uint32_t bL = bH + BPL;
        #pragma unroll
        for (int ks = 0; ks < KCH / 16; ks++) {
            int kc = ks * 16;
            if (BIG) {
                uint32_t ah[FD][4], al[FD][4];
                #pragma unroll
                for (int f = 0; f < FD; f++) {
                    uint32_t aoff = (uint32_t)((wm * 32 + f * 16 + rin + ((seg & 1) << 3) + s) * P
                                               + kc + ((seg >> 1) << 3)) * 2;
                    ldsm4(ah[f][0], ah[f][1], ah[f][2], ah[f][3], aH + aoff);
                    ldsm4(al[f][0], al[f][1], al[f][2], al[f][3], aL + aoff);
                }
                #pragma unroll
                for (int g = 0; g < 4; g++) {
                    uint32_t boff = (uint32_t)(((bt * COUT) + wn * 64 + g * 16 + rin + ((seg >> 1) << 3)) * P
                                               + kc + ((seg & 1) << 3)) * 2;
                    uint32_t bh0, bh1, bh2, bh3, bl0, bl1, bl2, bl3;
                    ldsm4(bh0, bh1, bh2, bh3, bH + boff);
                    ldsm4(bl0, bl1, bl2, bl3, bL + boff);
                    #pragma unroll
                    for (int f = 0; f < FD; f++) {
                        mma16816(d[f][2 * g],     ah[f][0], ah[f][1], ah[f][2], ah[f][3], bh0, bh1);
                        mma16816(d[f][2 * g],     ah[f][0], ah[f][1], ah[f][2], ah[f][3], bl0, bl1);
                        mma16816(d[f][2 * g],     al[f][0], al[f][1], al[f][2], al[f][3], bh0, bh1);
                        mma16816(d[f][2 * g + 1], ah[f][0], ah[f][1], ah[f][2], ah[f][3], bh2, bh3);
                        mma16816(d[f][2 * g + 1], ah[f][0], ah[f][1], ah[f][2], ah[f][3], bl2, bl3);
                        mma16816(d[f][2 * g + 1], al[f][0], al[f][1], al[f][2], al[f][3], bh2, bh3);
                    }
                }
            } else {
                uint32_t aoff = (uint32_t)((w * 16 + rin + ((seg & 1) << 3) + s) * P
                                           + kc + ((seg >> 1) << 3)) * 2;
                uint32_t ah0, ah1, ah2, ah3, al0, al1, al2, al3;
                ldsm4(ah0, ah1, ah2, ah3, aH + aoff);
                ldsm4(al0, al1, al2, al3, aL + aoff);
                #pragma unroll
                for (int g = 0; g < 2; g++) {
                    uint32_t boff = (uint32_t)(((bt * COUT) + g * 16 + rin + ((seg >> 1) << 3)) * P
                                               + kc + ((seg & 1) << 3)) * 2;
                    uint32_t bh0, bh1, bh2, bh3, bl0, bl1, bl2, bl3;
                    ldsm4(bh0, bh1, bh2, bh3, bH + boff);
                    ldsm4(bl0, bl1, bl2, bl3, bL + boff);
                    mma16816(d[0][2 * g],     ah0, ah1, ah2, ah3, bh0, bh1);
                    mma16816(d[0][2 * g],     ah0, ah1, ah2, ah3, bl0, bl1);
                    mma16816(d[0][2 * g],     al0, al1, al2, al3, bh0, bh1);
                    mma16816(d[0][2 * g + 1], ah0, ah1, ah2, ah3, bh2, bh3);
                    mma16816(d[0][2 * g + 1], ah0, ah1, ah2, ah3, bl2, bl3);
                    mma16816(d[0][2 * g + 1], al0, al1, al2, al3, bh2, bh3);
                }
            }
        }
    };

    auto epilogue = [&](int row0t) {
        if (HEADS) {
            float p1[2][2] = {}, p2[2][2] = {}, p3[2][2] = {};
            #pragma unroll
            for (int f = 0; f < FD; f++)
                #pragma unroll
                for (int t = 0; t < TD; t++) {
                    int n = wn * 64 + t * 8 + qid * 2;
                    float b0 = bias[n], b1 = bias[n + 1];
                    float v00 = fmaxf(d[f][t][0] + b0, 0.0f);
                    float v01 = fmaxf(d[f][t][1] + b1, 0.0f);
                    float v10 = fmaxf(d[f][t][2] + b0, 0.0f);
                    float v11 = fmaxf(d[f][t][3] + b1, 0.0f);
                    float wa0 = HWpi[n], wa1 = HWpi[n + 1];
                    float wb0 = HWn[n],  wb1 = HWn[n + 1];
                    float wc0 = HWp[n],  wc1 = HWp[n + 1];
                    p1[f][0] += v00 * wa0 + v01 * wa1;  p1[f][1] += v10 * wa0 + v11 * wa1;
                    p2[f][0] += v00 * wb0 + v01 * wb1;  p2[f][1] += v10 * wb0 + v11 * wb1;
                    p3[f][0] += v00 * wc0 + v01 * wc1;  p3[f][1] += v10 * wc0 + v11 * wc1;
                }
            #pragma unroll
            for (int f = 0; f < 2; f++)
                #pragma unroll
                for (int h = 0; h < 2; h++) {
                    p1[f][h] += __shfl_xor_sync(0xffffffffu, p1[f][h], 1);
                    p1[f][h] += __shfl_xor_sync(0xffffffffu, p1[f][h], 2);
                    p2[f][h] += __shfl_xor_sync(0xffffffffu, p2[f][h], 1);
                    p2[f][h] += __shfl_xor_sync(0xffffffffu, p2[f][h], 2);
                    p3[f][h] += __shfl_xor_sync(0xffffffffu, p3[f][h], 1);
                    p3[f][h] += __shfl_xor_sync(0xffffffffu, p3[f][h], 2);
                }
            if (wn == 0 && qid == 0) {
                #pragma unroll
                for (int f = 0; f < 2; f++) {
                    int r = wm * 32 + f * 16 + gid;
                    hbuf[r] = p1[f][0];        hbuf[r + 8] = p1[f][1];
                    hbuf[128 + r] = p2[f][0];  hbuf[128 + r + 8] = p2[f][1];
                    hbuf[256 + r] = p3[f][0];  hbuf[256 + r + 8] = p3[f][1];
                }
            }
            __syncthreads();
            if (wn == 1 && qid == 0) {
                #pragma unroll
                for (int f = 0; f < 2; f++)
                    #pragma unroll
                    for (int h = 0; h < 2; h++) {
                        int r = wm * 32 + f * 16 + gid + h * 8;
                        int rg = row0t + r;
                        float z1 = hbuf[r] + p1[f][h] + Hbpi[0];
                        float z2 = hbuf[128 + r] + p2[f][h] + Hbn[0];
                        float z3 = hbuf[256 + r] + p3[f][h] + Hbp[0];
                        hout[rg]            = 1.0f / (1.0f + expf(-z1));
                        hout[TOTN + rg]     = (z2 > 0.0f) ? (z2 + log1pf(expf(-z2))) : log1pf(expf(z2));
                        hout[2 * TOTN + rg] = 1.0f / (1.0f + expf(-z3));
                    }
            }
            __syncthreads();
        } else {
            #pragma unroll
            for (int f = 0; f < FD; f++) {
                int r0 = row0t + (BIG ? (wm * 32 + f * 16) : (w * 16)) + gid;
                #pragma unroll
                for (int t = 0; t < TD; t++) {
                    int n = (BIG ? wn * 64 : 0) + t * 8 + qid * 2;
                    float2 v0 = make_float2(d[f][t][0], d[f][t][1]);
                    float2 v1 = make_float2(d[f][t][2], d[f][t][3]);
                    if (HASBIAS) {
                        float bx = bias[n], by = bias[n + 1];
                        v0.x += bx; v0.y += by;
                        v1.x += bx; v1.y += by;
                    }
                    if (HASRELU) {
                        v0.x = fmaxf(v0.x, 0.0f); v0.y = fmaxf(v0.y, 0.0f);
                        v1.x = fmaxf(v1.x, 0.0f); v1.y = fmaxf(v1.y, 0.0f);
                    }
                    if (OUTPLANES) {
                        bf16 h0 = __float2bfloat16(v0.x), h1 = __float2bfloat16(v0.y);
                        bf16 h2 = __float2bfloat16(v1.x), h3 = __float2bfloat16(v1.y);
                        *(uint32_t*)&OH[(size_t)r0 * COUT + n] = pack_bf(v0.x, v0.y);
                        *(uint32_t*)&OL[(size_t)r0 * COUT + n] = pack_bf(v0.x - __bfloat162float(h0),
                                                                         v0.y - __bfloat162float(h1));
                        *(uint32_t*)&OH[(size_t)(r0 + 8) * COUT + n] = pack_bf(v1.x, v1.y);
                        *(uint32_t*)&OL[(size_t)(r0 + 8) * COUT + n] = pack_bf(v1.x - __bfloat162float(h2),
                                                                               v1.y - __bfloat162float(h3));
                    } else {
                        *(float2*)&OUT[(size_t)r0 * COUT + n]       = v0;
                        *(float2*)&OUT[(size_t)(r0 + 8) * COUT + n] = v1;
                    }
                }
            }
        }
    };

    if (PIPE) {
        stage_A(blockIdx.x * TILES * 128, 0, 0);
        stage_B_all(0);
        CP_COMMIT();
        for (int t = 0; t < TILES; t++) {
            int row0t = (blockIdx.x * TILES + t) * 128;
            CP_WAIT0();
            __syncthreads();
            if (t + 1 < TILES) {
                stage_A(row0t + 128, 0, (t + 1) & 1);
                CP_COMMIT();
            }
            reset_acc();
            uint32_t aH = sb + (uint32_t)((t & 1) * 2) * ABUFB;
            uint32_t aL = aH + ABUFB;
            #pragma unroll
            for (int s = 0; s < TAPS; s++) mma_chunk(aH, aL, s, ALLTAPS ? s : 0, 0);
            epilogue(row0t);
            __syncthreads();
        }
    } else {
        for (int t = 0; t < TILES; t++) {
            int row0t = (blockIdx.x * TILES + t) * 128;
            reset_acc();
            for (int c = 0; c < NCHC; c++) {
                int c0 = c * KCH;
                __syncthreads();
                stage_A(row0t, c0, 0);
                if (ALLTAPS) stage_B_all(c0);
                else if (TAPS == 1) { if (t == 0) stage_B_all(c0); }
                else stage_B_tap(0, c0, 0);
                CP_COMMIT(); CP_WAIT0();
                __syncthreads();
                #pragma unroll
                for (int s = 0; s < TAPS; s++) {
                    if (BDB && s + 1 < TAPS) {
                        stage_B_tap(s + 1, c0, (s + 1) & 1);
                        CP_COMMIT();
                    }
                    mma_chunk(sb, sb + ABUFB, s, ALLTAPS ? s : 0, BDB ? (s & 1) : 0);
                    if (BDB && s + 1 < TAPS) {
                        CP_WAIT0();
                        __syncthreads();
                    }
                }
            }
            __syncthreads();
            epilogue(row0t);
        }
    }
}

// ---------------- CSR build ----------------
__device__ __forceinline__ int edge_at(const void* e, int idx, int is64) {
    if (is64) return (int)((const long long*)e)[idx];
    return ((const int*)e)[idx];
}
__global__ void count_kernel(const void* edges, int* cnt, int E) {
    int is64 = g_is64;
    int i  = blockIdx.x * blockDim.x + threadIdx.x;
    int st = gridDim.x * blockDim.x;
    for (; i < E; i += st) {
        int d = edge_at(edges, E + i, is64);
        atomicAdd(&cnt[d], 1);
    }
}
__global__ void __launch_bounds__(256)
scan_partial_kernel(const int* __restrict__ cnt, int* part) {
    __shared__ int sh[8];
    int tid = threadIdx.x;
    int v = cnt[blockIdx.x * SCCH + tid];
    #pragma unroll
    for (int o = 16; o > 0; o >>= 1) v += __shfl_xor_sync(0xffffffffu, v, o);
    if ((tid & 31) == 0) sh[tid >> 5] = v;
    __syncthreads();
    if (tid < 8) {
        int s = sh[tid];
        #pragma unroll
        for (int o = 4; o > 0; o >>= 1) s += __shfl_xor_sync(0xffu, s, o, 8);
        if (tid == 0) part[blockIdx.x] = s;
    }
}
__global__ void __launch_bounds__(256)
scan_emit_kernel(const int* __restrict__ cnt, const int* __restrict__ part,
                 int* row_ptr, int* cursor, float* dinv) {
    __shared__ int wsum[8];
    __shared__ int bsum[8];
    int tid  = threadIdx.x;
    int lane = tid & 31;
    int wid  = tid >> 5;

    int bs = 0;
    for (int i = tid; i < blockIdx.x; i += 256) bs += part[i];
    #pragma unroll
    for (int o = 16; o > 0; o >>= 1) bs += __shfl_xor_sync(0xffffffffu, bs, o);
    if (lane == 0) bsum[wid] = bs;
    __syncthreads();
    if (tid == 0) {
        int b = 0;
        #pragma unroll
        for (int k = 0; k < 8; k++) b += bsum[k];
        bsum[0] = b;
    }
    __syncthreads();
    int base = bsum[0];

    int i = blockIdx.x * SCCH + tid;
    int c = cnt[i];
    int v = c;
    #pragma unroll
    for (int o = 1; o < 32; o <<= 1) {
        int u = __shfl_up_sync(0xffffffffu, v, o);
        if (lane >= o) v += u;
    }
    if (lane == 31) wsum[wid] = v;
    __syncthreads();
    if (wid == 0 && lane < 8) {
        int s = wsum[lane];
        #pragma unroll
        for (int o = 1; o < 8; o <<= 1) {
            int u = __shfl_up_sync(0xffu, s, o, 8);
            if (lane >= o) s += u;
        }
        wsum[lane] = s;
    }
    __syncthreads();
    int excl = v - c + (wid > 0 ? wsum[wid - 1] : 0);
    int run = base + excl;
    row_ptr[i] = run;
    cursor[i]  = run;
    dinv[i]    = rsqrtf((float)c + 1.0f);
    if (i == TOTN - 1) row_ptr[TOTN] = run + c;
}
__global__ void fill_kernel(const void* edges, int* cursor, int* adj, int E) {
    int is64 = g_is64;
    int i  = blockIdx.x * blockDim.x + threadIdx.x;
    int st = gridDim.x * blockDim.x;
    for (; i < E; i += st) {
        int s = edge_at(edges, i, is64);
        int d = edge_at(edges, E + i, is64);
        int pos = atomicAdd(&cursor[d], 1);
        adj[pos] = s;
    }
}

// ---------------- CSR gather + fused epilogue ----------------
template <int D, int BIASRELU, int OUTPLANES>
__global__ void gather_kernel(const int* __restrict__ row_ptr, const int* __restrict__ adj,
                              const float* __restrict__ dinv, const float* __restrict__ X,
                              const float* __restrict__ bias, float* __restrict__ OUT,
                              bf16* __restrict__ OH, bf16* __restrict__ OL, int n) {
    int lane = threadIdx.x & 31;
    int node = (blockIdx.x * blockDim.x + threadIdx.x) >> 5;
    if (node >= n) return;
    int beg = row_ptr[node];
    int end = row_ptr[node + 1];
    float di = dinv[node];
    float c  = di * di;
    if (D == 64) {
        float ax = 0.0f, ay = 0.0f;
        #pragma unroll 4
        for (int j = beg; j < end; j++) {
            int s = adj[j];
            float ws = __ldg(&dinv[s]);
            float2 v = ((const float2*)(X + (size_t)s * 64))[lane];
            ax = fmaf(ws, v.x, ax);
            ay = fmaf(ws, v.y, ay);
        }
        float2 xv = ((const float2*)(X + (size_t)node * 64))[lane];
        float2 o;
        o.x = c * (ax + xv.x);
        o.y = c * (ay + xv.y);
        if (BIASRELU) {
            o.x = fmaxf(o.x + bias[2 * lane],     0.0f);
            o.y = fmaxf(o.y + bias[2 * lane + 1], 0.0f);
        }
        if (OUTPLANES) {
            bf16 hx = __float2bfloat16(o.x), hy = __float2bfloat16(o.y);
            *(uint32_t*)&OH[(size_t)node * 64 + 2 * lane] = pack_bf(o.x, o.y);
            *(uint32_t*)&OL[(size_t)node * 64 + 2 * lane] = pack_bf(o.x - __bfloat162float(hx),
                                                                    o.y - __bfloat162float(hy));
        } else {
            ((float2*)(OUT + (size_t)node * 64))[lane] = o;
        }
    } else {
        float acc = 0.0f;
        #pragma unroll 4
        for (int j = beg; j < end; j++) {
            int s = adj[j];
            float ws = __ldg(&dinv[s]);
            acc = fmaf(ws, X[(size_t)s * 32 + lane], acc);
        }
        float v = c * (acc + X[(size_t)node * 32 + lane]);
        if (BIASRELU) v = fmaxf(v + bias[lane], 0.0f);
        if (OUTPLANES) {
            bf16 h = __float2bfloat16(v);
            OH[(size_t)node * 32 + lane] = h;
            OL[(size_t)node * 32 + lane] = __float2bfloat16(v - __bfloat162float(h));
        } else {
            OUT[(size_t)node * 32 + lane] = v;
        }
    }
}

// ---------------- launch ----------------
extern "C" void kernel_launch(void* const* d_in, const int* in_sizes, int n_in,
                              void* d_out, int out_size) {
    const float* x     = (const float*)d_in[0];
    const void*  edges = d_in[1];
    const float* W1  = (const float*)d_in[3];  const float* b1  = (const float*)d_in[4];
    const float* W2  = (const float*)d_in[5];  const float* b2  = (const float*)d_in[6];
    const float* W3  = (const float*)d_in[7];  const float* b3  = (const float*)d_in[8];
    const float* tW1 = (const float*)d_in[9];  const float* tb1 = (const float*)d_in[10];
    const float* tW2 = (const float*)d_in[11]; const float* tb2 = (const float*)d_in[12];
    const float* tW3 = (const float*)d_in[13]; const float* tb3 = (const float*)d_in[14];
    const float* Wpi = (const float*)d_in[15]; const float* bpi = (const float*)d_in[16];
    const float* Wn  = (const float*)d_in[17]; const float* bn  = (const float*)d_in[18];
    const float* Wp  = (const float*)d_in[19]; const float* bp  = (const float*)d_in[20];
    float* out = (float*)d_out;

    const int TOT = in_sizes[0] / FDIM;
    const int E   = in_sizes[1] / 2;

    float *dinv, *H2raw, *H2;
    int *cnt, *rowp, *curs, *adj, *part;
    bf16 *A1h, *A1l, *H1h, *H1l, *A3h, *A3l, *H3h, *H3l, *C1h, *C1l, *C2h, *C2l;
    bf16 *W1h, *W1l, *W2h, *W2l, *W3h, *W3l, *T1h, *T1l, *T2h, *T2l, *T3h, *T3l;
    cudaGetSymbolAddress((void**)&dinv,  g_dinv);
    cudaGetSymbolAddress((void**)&cnt,   g_cnt);
    cudaGetSymbolAddress((void**)&rowp,  g_rowp);
    cudaGetSymbolAddress((void**)&curs,  g_curs);
    cudaGetSymbolAddress((void**)&adj,   g_adj);
    cudaGetSymbolAddress((void**)&part,  g_part);
    cudaGetSymbolAddress((void**)&A1h,   g_A1h);  cudaGetSymbolAddress((void**)&A1l, g_A1l);
    cudaGetSymbolAddress((void**)&H1h,   g_H1h);  cudaGetSymbolAddress((void**)&H1l, g_H1l);
    cudaGetSymbolAddress((void**)&A3h,   g_A3h);  cudaGetSymbolAddress((void**)&A3l, g_A3l);
    cudaGetSymbolAddress((void**)&H3h,   g_H3h);  cudaGetSymbolAddress((void**)&H3l, g_H3l);
    cudaGetSymbolAddress((void**)&C1h,   g_C1h);  cudaGetSymbolAddress((void**)&C1l, g_C1l);
    cudaGetSymbolAddress((void**)&C2h,   g_C2h);  cudaGetSymbolAddress((void**)&C2l, g_C2l);
    cudaGetSymbolAddress((void**)&H2raw, g_H2raw);
    cudaGetSymbolAddress((void**)&H2,    g_H2);
    cudaGetSymbolAddress((void**)&W1h, g_W1h); cudaGetSymbolAddress((void**)&W1l, g_W1l);
    cudaGetSymbolAddress((void**)&W2h, g_W2h); cudaGetSymbolAddress((void**)&W2l, g_W2l);
    cudaGetSymbolAddress((void**)&W3h, g_W3h); cudaGetSymbolAddress((void**)&W3l, g_W3l);
    cudaGetSymbolAddress((void**)&T1h, g_T1h); cudaGetSymbolAddress((void**)&T1l, g_T1l);
    cudaGetSymbolAddress((void**)&T2h, g_T2h); cudaGetSymbolAddress((void**)&T2l, g_T2l);
    cudaGetSymbolAddress((void**)&T3h, g_T3h); cudaGetSymbolAddress((void**)&T3l, g_T3l);

    const int gatherBlocks = (TOT * 32) / 256;
    const int grid2 = TOT / 256;   // TILES=2
    const int grid4 = TOT / 512;   // TILES=4

    // smem sizes (bytes)
    const int SM_G1 = 4 * (128 * 72 * 2)  + 2 * (128 * 72 * 2);              // 110592 (PIPE)
    const int SM_G2 = 2 * (128 * 136 * 2) + 2 * (32 * 136 * 2);              //  87040
    const int SM_G3 = 4 * (128 * 40 * 2)  + 2 * (128 * 40 * 2);              //  61440 (PIPE)
    const int SM_C1 = 2 * (130 * 72 * 2)  + 4 * (128 * 72 * 2);              // 111168 (B dbl-buf)
    const int SM_C2 = 2 * (130 * 72 * 2)  + 2 * (3 * 32 * 72 * 2);           //  65088
    const int SM_C3 = 4 * (130 * 40 * 2)  + 2 * (3 * 128 * 40 * 2) + 1536;   // 104576 (PIPE)

    cudaFuncSetAttribute(mma_layer<64, 128, 1, 64, 1, 1, 1, 0, 4, 1>,  cudaFuncAttributeMaxDynamicSharedMemorySize, SM_G1);
    cudaFuncSetAttribute(mma_layer<128, 32, 1, 128, 0, 0, 0, 0, 4, 0>, cudaFuncAttributeMaxDynamicSharedMemorySize, SM_G2);
    cudaFuncSetAttribute(mma_layer<32, 128, 1, 32, 1, 1, 1, 0, 4, 1>,  cudaFuncAttributeMaxDynamicSharedMemorySize, SM_G3);
    cudaFuncSetAttribute(mma_layer<128, 128, 3, 64, 1, 1, 1, 0, 2, 0>, cudaFuncAttributeMaxDynamicSharedMemorySize, SM_C1);
    cudaFuncSetAttribute(mma_layer<128, 32, 3, 64, 1, 1, 1, 0, 2, 0>,  cudaFuncAttributeMaxDynamicSharedMemorySize, SM_C2);
    cudaFuncSetAttribute(mma_layer<32, 128, 3, 32, 1, 1, 0, 1, 4, 1>,  cudaFuncAttributeMaxDynamicSharedMemorySize, SM_C3);

    // ---- prep + CSR build ----
    prep_kernel<<<256, 256>>>(cnt, TOT, (const unsigned int*)edges, W1, W2, W3, tW1, tW2, tW3);
    count_kernel<<<2048, 256>>>(edges, cnt, E);
    scan_partial_kernel<<<SCB, 256>>>(cnt, part);
    scan_emit_kernel<<<SCB, 256>>>(cnt, part, rowp, curs, dinv);
    fill_kernel<<<2048, 256>>>(edges, curs, adj, E);

    // ---- GCN stack ----
    gather_kernel<64, 0, 1><<<gatherBlocks, 256>>>(rowp, adj, dinv, x, nullptr, nullptr, A1h, A1l, TOT);
    mma_layer<64, 128, 1, 64, 1, 1, 1, 0, 4, 1><<<grid4, 256, SM_G1>>>(
        A1h, A1l, W1h, W1l, b1, nullptr, H1h, H1l,
        nullptr, nullptr, nullptr, nullptr, nullptr, nullptr, nullptr);
    mma_layer<128, 32, 1, 128, 0, 0, 0, 0, 4, 0><<<grid4, 256, SM_G2>>>(
        H1h, H1l, W2h, W2l, nullptr, H2raw, nullptr, nullptr,
        nullptr, nullptr, nullptr, nullptr, nullptr, nullptr, nullptr);
    gather_kernel<32, 1, 0><<<gatherBlocks, 256>>>(rowp, adj, dinv, H2raw, b2, H2, nullptr, nullptr, TOT);
    gather_kernel<32, 0, 1><<<gatherBlocks, 256>>>(rowp, adj, dinv, H2, nullptr, nullptr, A3h, A3l, TOT);
    mma_layer<32, 128, 1, 32, 1, 1, 1, 0, 4, 1><<<grid4, 256, SM_G3>>>(
        A3h, A3l, W3h, W3l, b3, nullptr, H3h, H3l,
        nullptr, nullptr, nullptr, nullptr, nullptr, nullptr, nullptr);

    // ---- temporal conv stack (k=3, pad=1); conv3 fuses the 3 heads ----
    mma_layer<128, 128, 3, 64, 1, 1, 1, 0, 2, 0><<<grid2, 256, SM_C1>>>(
        H3h, H3l, T1h, T1l, tb1, nullptr, C1h, C1l,
        nullptr, nullptr, nullptr, nullptr, nullptr, nullptr, nullptr);
    mma_layer<128, 32, 3, 64, 1, 1, 1, 0, 2, 0><<<grid2, 256, SM_C2>>>(
        C1h, C1l, T2h, T2l, tb2, nullptr, C2h, C2l,
        nullptr, nullptr, nullptr, nullptr, nullptr, nullptr, nullptr);
    mma_layer<32, 128, 3, 32, 1, 1, 0, 1, 4, 1><<<grid4, 256, SM_C3>>>(
        C2h, C2l, T3h, T3l, tb3, nullptr, nullptr, nullptr,
        Wpi, Wn, Wp, bpi, bn, bp, out);
}

// round 14
// speedup vs baseline: 1.0634x; 1.0634x over previous
#include <cuda_runtime.h>
#include <cuda_bf16.h>
#include <math.h>
#include <stdint.h>

// ---------------- problem constants ----------------
#define TOTN   131072      // B*N nodes
#define EMAX   1048576
#define FDIM   64
#define HSD    128
#define RSD    32
#define NPG    4096        // nodes per graph (temporal length)
#define SCB    512         // scan blocks
#define SCCH   (TOTN / SCB)

typedef __nv_bfloat16 bf16;

// ---------------- device scratch (no cudaMalloc allowed) ----------------
__device__ int   g_is64;
__device__ float g_dinv [TOTN];
__device__ int   g_cnt  [TOTN];
__device__ int   g_rowp [TOTN + 1];
__device__ int   g_curs [TOTN];
__device__ int   g_adj  [EMAX];
__device__ int   g_part [SCB];
// bf16 hi/lo planes for activations
__device__ __align__(16) bf16 g_A1h[TOTN * FDIM], g_A1l[TOTN * FDIM];
__device__ __align__(16) bf16 g_H1h[TOTN * HSD],  g_H1l[TOTN * HSD];
__device__ __align__(16) bf16 g_A3h[TOTN * RSD],  g_A3l[TOTN * RSD];
__device__ __align__(16) bf16 g_H3h[TOTN * HSD],  g_H3l[TOTN * HSD];
__device__ __align__(16) bf16 g_C1h[TOTN * HSD],  g_C1l[TOTN * HSD];
__device__ __align__(16) bf16 g_C2h[TOTN * RSD],  g_C2l[TOTN * RSD];
// fp32 intermediates
__device__ float g_H2raw[TOTN * RSD];
__device__ float g_H2   [TOTN * RSD];
// weight planes (k-major [tap][COUT][CIN])
__device__ __align__(16) bf16 g_W1h[128 * 64],      g_W1l[128 * 64];
__device__ __align__(16) bf16 g_W2h[32 * 128],      g_W2l[32 * 128];
__device__ __align__(16) bf16 g_W3h[128 * 32],      g_W3l[128 * 32];
__device__ __align__(16) bf16 g_T1h[3 * 128 * 128], g_T1l[3 * 128 * 128];
__device__ __align__(16) bf16 g_T2h[3 * 32 * 128],  g_T2l[3 * 32 * 128];
__device__ __align__(16) bf16 g_T3h[3 * 128 * 32],  g_T3l[3 * 128 * 32];

__device__ __forceinline__ uint32_t pack_bf(float a, float b) {
    __nv_bfloat162 t;
    t.x = __float2bfloat16(a);
    t.y = __float2bfloat16(b);
    return *reinterpret_cast<uint32_t*>(&t);
}
__device__ __forceinline__ uint32_t smem_u32(const void* p) {
    uint32_t a;
    asm("{ .reg .u64 t; cvta.to.shared.u64 t, %1; cvt.u32.u64 %0, t; }" : "=r"(a) : "l"(p));
    return a;
}
__device__ __forceinline__ void mma16816(float* d, uint32_t a0, uint32_t a1, uint32_t a2,
                                         uint32_t a3, uint32_t b0, uint32_t b1) {
    asm volatile(
        "mma.sync.aligned.m16n8k16.row.col.f32.bf16.bf16.f32 "
        "{%0,%1,%2,%3}, {%4,%5,%6,%7}, {%8,%9}, {%0,%1,%2,%3};"
        : "+f"(d[0]), "+f"(d[1]), "+f"(d[2]), "+f"(d[3])
        : "r"(a0), "r"(a1), "r"(a2), "r"(a3), "r"(b0), "r"(b1));
}
__device__ __forceinline__ void ldsm4(uint32_t& r0, uint32_t& r1, uint32_t& r2, uint32_t& r3,
                                      uint32_t addr) {
    asm volatile("ldmatrix.sync.aligned.m8n8.x4.shared.b16 {%0,%1,%2,%3}, [%4];"
                 : "=r"(r0), "=r"(r1), "=r"(r2), "=r"(r3) : "r"(addr));
}
__device__ __forceinline__ void cp16(uint32_t s, const void* g, bool p) {
    asm volatile("cp.async.cg.shared.global [%0], [%1], 16, %2;"
                 :: "r"(s), "l"(g), "r"(p ? 16 : 0));
}
#define CP_COMMIT() asm volatile("cp.async.commit_group;" ::: "memory")
#define CP_WAIT0()  asm volatile("cp.async.wait_group 0;" ::: "memory")

// ---------------- weight plane precompute ----------------
__device__ void wlin(const float* W, bf16* WH, bf16* WL, int CIN, int COUT, int tid, int nt) {
    for (int i = tid; i < CIN * COUT; i += nt) {
        int n = i / CIN, k = i % CIN;
        float w = W[(size_t)k * COUT + n];
        bf16 h = __float2bfloat16(w);
        WH[i] = h;
        WL[i] = __float2bfloat16(w - __bfloat162float(h));
    }
}
__device__ void wconv(const float* W, bf16* WH, bf16* WL, int CIN, int COUT, int tid, int nt) {
    for (int i = tid; i < 3 * CIN * COUT; i += nt) {
        int s = i / (CIN * COUT);
        int n = (i / CIN) % COUT;
        int k = i % CIN;
        float w = W[((size_t)n * CIN + k) * 3 + s];
        bf16 h = __float2bfloat16(w);
        WH[i] = h;
        WL[i] = __float2bfloat16(w - __bfloat162float(h));
    }
}
__global__ void prep_kernel(int* cnt, int n, const unsigned int* e,
                            const float* W1, const float* W2, const float* W3,
                            const float* T1, const float* T2, const float* T3) {
    int tid = blockIdx.x * blockDim.x + threadIdx.x;
    int nt  = gridDim.x * blockDim.x;
    for (int i = tid; i < n; i += nt) cnt[i] = 0;
    if (tid == 0) {
        int ok = 1;
        #pragma unroll 1
        for (int k = 0; k < 64; k++)
            if (e[2 * k + 1] != 0u) { ok = 0; break; }
        g_is64 = ok;
    }
    wlin(W1, g_W1h, g_W1l, 64, 128, tid, nt);
    wlin(W2, g_W2h, g_W2l, 128, 32, tid, nt);
    wlin(W3, g_W3h, g_W3l, 32, 128, tid, nt);
    wconv(T1, g_T1h, g_T1l, 128, 128, tid, nt);
    wconv(T2, g_T2h, g_T2l, 128, 32, tid, nt);
    wconv(T3, g_T3h, g_T3l, 32, 128, tid, nt);
}

// =========== unified dense layer on tensor cores ===========
template <int CIN, int COUT, int TAPS, int KCH, int HASBIAS, int HASRELU,
          int OUTPLANES, int HEADS, int TILES, int PIPE>
__global__ void __launch_bounds__(256, 2)
mma_layer(const bf16* __restrict__ XH, const bf16* __restrict__ XL,
          const bf16* __restrict__ WH, const bf16* __restrict__ WL,
          const float* __restrict__ bias,
          float* __restrict__ OUT, bf16* __restrict__ OH, bf16* __restrict__ OL,
          const float* __restrict__ HWpi, const float* __restrict__ HWn,
          const float* __restrict__ HWp, const float* __restrict__ Hbpi,
          const float* __restrict__ Hbn, const float* __restrict__ Hbp,
          float* __restrict__ hout) {
    constexpr int NCHC = CIN / KCH;
    constexpr int P    = KCH + 8;
    constexpr int HALO = (TAPS == 3) ? 1 : 0;
    constexpr int RSTG = 128 + 2 * HALO;
    constexpr bool BIG = (COUT == 128);
    constexpr bool ALLTAPS = (TAPS == 3) && (COUT == 32 || CIN == 32);
    constexpr bool BDB = (TAPS == 3) && !ALLTAPS && !PIPE;   // B double-buffer (conv1)
    constexpr int BTAPS = ALLTAPS ? 3 : 1;
    constexpr int U4   = KCH / 8;
    constexpr int FD   = BIG ? 2 : 1;
    constexpr int TD   = BIG ? 8 : 4;
    constexpr int NBUF = PIPE ? 2 : 1;
    constexpr int ABUFB  = RSTG * P * 2;
    constexpr int OFF_B  = NBUF * 2 * ABUFB;
    constexpr int BPL    = BTAPS * COUT * P * 2;
    constexpr int NBB    = BDB ? 2 : 1;
    constexpr int OFF_HB = OFF_B + NBB * 2 * BPL;

    extern __shared__ __align__(16) char smem[];
    const uint32_t sb = smem_u32(smem);
    float* hbuf = (float*)(smem + OFF_HB);

    int tid  = threadIdx.x;
    int w    = tid >> 5;
    int lane = tid & 31;
    int gid  = lane >> 2;
    int qid  = lane & 3;
    int seg  = lane >> 3;
    int rin  = lane & 7;
    int wm   = BIG ? (w & 3) : w;
    int wn   = BIG ? (w >> 2) : 0;

    float d[FD][TD][4];

    auto reset_acc = [&]() {
        #pragma unroll
        for (int f = 0; f < FD; f++)
            #pragma unroll
            for (int t = 0; t < TD; t++)
                #pragma unroll
                for (int i = 0; i < 4; i++) d[f][t][i] = 0.0f;
    };

    auto stage_A = [&](int trow0, int c0, int b) {
        int gbl = (trow0 / NPG) * NPG;
        uint32_t dh = sb + (uint32_t)(b * 2) * ABUFB;
        uint32_t dl = dh + ABUFB;
        for (int idx = tid; idx < RSTG * U4; idx += 256) {
            int r = idx / U4, j = (idx % U4) * 8;
            long src = (long)trow0 - HALO + r;
            bool ok = (!HALO) || (src >= gbl && src < (long)gbl + NPG);
            long sc = ok ? src : (long)trow0;
            cp16(dh + (uint32_t)(r * P + j) * 2, XH + sc * CIN + c0 + j, ok);
            cp16(dl + (uint32_t)(r * P + j) * 2, XL + sc * CIN + c0 + j, ok);
        }
    };
    auto stage_B_all = [&](int c0) {
        for (int idx = tid; idx < BTAPS * COUT * U4; idx += 256) {
            int n2 = idx / U4, j = (idx % U4) * 8;
            cp16(sb + OFF_B       + (uint32_t)(n2 * P + j) * 2, WH + (size_t)n2 * CIN + c0 + j, true);
            cp16(sb + OFF_B + BPL + (uint32_t)(n2 * P + j) * 2, WL + (size_t)n2 * CIN + c0 + j, true);
        }
    };
    auto stage_B_tap = [&](int s, int c0, int bb) {
        uint32_t bh = sb + OFF_B + (uint32_t)bb * 2 * BPL;
        for (int idx = tid; idx < COUT * U4; idx += 256) {
            int n = idx / U4, j = (idx % U4) * 8;
            cp16(bh       + (uint32_t)(n * P + j) * 2, WH + ((size_t)s * COUT + n) * CIN + c0 + j, true);
            cp16(bh + BPL + (uint32_t)(n * P + j) * 2, WL + ((size_t)s * COUT + n) * CIN + c0 + j, true);
        }
    };

    auto mma_chunk = [&](uint32_t aH, uint32_t aL, int s, int bt, int bb) {
        uint32_t bH = sb + OFF_B + (uint32_t)bb * 2 * BPL;
        uint32_t bL = bH + BPL;
        #pragma unroll
        for (int ks = 0; ks < KCH / 16; ks++) {
            int kc = ks * 16;
            if (BIG) {
                uint32_t ah[FD][4], al[FD][4];
                #pragma unroll
                for (int f = 0; f < FD; f++) {
                    uint32_t aoff = (uint32_t)((wm * 32 + f * 16 + rin + ((seg & 1) << 3) + s) * P
                                               + kc + ((seg >> 1) << 3)) * 2;
                    ldsm4(ah[f][0], ah[f][1], ah[f][2], ah[f][3], aH + aoff);
                    ldsm4(al[f][0], al[f][1], al[f][2], al[f][3], aL + aoff);
                }
                #pragma unroll
                for (int g = 0; g < 4; g++) {
                    uint32_t boff = (uint32_t)(((bt * COUT) + wn * 64 + g * 16 + rin + ((seg >> 1) << 3)) * P
                                               + kc + ((seg & 1) << 3)) * 2;
                    uint32_t bh0, bh1, bh2, bh3, bl0, bl1, bl2, bl3;
                    ldsm4(bh0, bh1, bh2, bh3, bH + boff);
                    ldsm4(bl0, bl1, bl2, bl3, bL + boff);
                    #pragma unroll
                    for (int f = 0; f < FD; f++) {
                        mma16816(d[f][2 * g],     ah[f][0], ah[f][1], ah[f][2], ah[f][3], bh0, bh1);
                        mma16816(d[f][2 * g],     ah[f][0], ah[f][1], ah[f][2], ah[f][3], bl0, bl1);
                        mma16816(d[f][2 * g],     al[f][0], al[f][1], al[f][2], al[f][3], bh0, bh1);
                        mma16816(d[f][2 * g + 1], ah[f][0], ah[f][1], ah[f][2], ah[f][3], bh2, bh3);
                        mma16816(d[f][2 * g + 1], ah[f][0], ah[f][1], ah[f][2], ah[f][3], bl2, bl3);
                        mma16816(d[f][2 * g + 1], al[f][0], al[f][1], al[f][2], al[f][3], bh2, bh3);
                    }
                }
            } else {
                uint32_t aoff = (uint32_t)((w * 16 + rin + ((seg & 1) << 3) + s) * P
                                           + kc + ((seg >> 1) << 3)) * 2;
                uint32_t ah0, ah1, ah2, ah3, al0, al1, al2, al3;
                ldsm4(ah0, ah1, ah2, ah3, aH + aoff);
                ldsm4(al0, al1, al2, al3, aL + aoff);
                #pragma unroll
                for (int g = 0; g < 2; g++) {
                    uint32_t boff = (uint32_t)(((bt * COUT) + g * 16 + rin + ((seg >> 1) << 3)) * P
                                               + kc + ((seg & 1) << 3)) * 2;
                    uint32_t bh0, bh1, bh2, bh3, bl0, bl1, bl2, bl3;
                    ldsm4(bh0, bh1, bh2, bh3, bH + boff);
                    ldsm4(bl0, bl1, bl2, bl3, bL + boff);
                    mma16816(d[0][2 * g],     ah0, ah1, ah2, ah3, bh0, bh1);
                    mma16816(d[0][2 * g],     ah0, ah1, ah2, ah3, bl0, bl1);
                    mma16816(d[0][2 * g],     al0, al1, al2, al3, bh0, bh1);
                    mma16816(d[0][2 * g + 1], ah0, ah1, ah2, ah3, bh2, bh3);
                    mma16816(d[0][2 * g + 1], ah0, ah1, ah2, ah3, bl2, bl3);
                    mma16816(d[0][2 * g + 1], al0, al1, al2, al3, bh2, bh3);
                }
            }
        }
    };

    auto epilogue = [&](int row0t) {
        if (HEADS) {
            float p1[2][2] = {}, p2[2][2] = {}, p3[2][2] = {};
            #pragma unroll
            for (int f = 0; f < FD; f++)
                #pragma unroll
                for (int t = 0; t < TD; t++) {
                    int n = wn * 64 + t * 8 + qid * 2;
                    float b0 = bias[n], b1 = bias[n + 1];
                    float v00 = fmaxf(d[f][t][0] + b0, 0.0f);
                    float v01 = fmaxf(d[f][t][1] + b1, 0.0f);
                    float v10 = fmaxf(d[f][t][2] + b0, 0.0f);
                    float v11 = fmaxf(d[f][t][3] + b1, 0.0f);
                    float wa0 = HWpi[n], wa1 = HWpi[n + 1];
                    float wb0 = HWn[n],  wb1 = HWn[n + 1];
                    float wc0 = HWp[n],  wc1 = HWp[n + 1];
                    p1[f][0] += v00 * wa0 + v01 * wa1;  p1[f][1] += v10 * wa0 + v11 * wa1;
                    p2[f][0] += v00 * wb0 + v01 * wb1;  p2[f][1] += v10 * wb0 + v11 * wb1;
                    p3[f][0] += v00 * wc0 + v01 * wc1;  p3[f][1] += v10 * wc0 + v11 * wc1;
                }
            #pragma unroll
            for (int f = 0; f < 2; f++)
                #pragma unroll
                for (int h = 0; h < 2; h++) {
                    p1[f][h] += __shfl_xor_sync(0xffffffffu, p1[f][h], 1);
                    p1[f][h] += __shfl_xor_sync(0xffffffffu, p1[f][h], 2);
                    p2[f][h] += __shfl_xor_sync(0xffffffffu, p2[f][h], 1);
                    p2[f][h] += __shfl_xor_sync(0xffffffffu, p2[f][h], 2);
                    p3[f][h] += __shfl_xor_sync(0xffffffffu, p3[f][h], 1);
                    p3[f][h] += __shfl_xor_sync(0xffffffffu, p3[f][h], 2);
                }
            if (wn == 0 && qid == 0) {
                #pragma unroll
                for (int f = 0; f < 2; f++) {
                    int r = wm * 32 + f * 16 + gid;
                    hbuf[r] = p1[f][0];        hbuf[r + 8] = p1[f][1];
                    hbuf[128 + r] = p2[f][0];  hbuf[128 + r + 8] = p2[f][1];
                    hbuf[256 + r] = p3[f][0];  hbuf[256 + r + 8] = p3[f][1];
                }
            }
            __syncthreads();
            if (wn == 1 && qid == 0) {
                #pragma unroll
                for (int f = 0; f < 2; f++)
                    #pragma unroll
                    for (int h = 0; h < 2; h++) {
                        int r = wm * 32 + f * 16 + gid + h * 8;
                        int rg = row0t + r;
                        float z1 = hbuf[r] + p1[f][h] + Hbpi[0];
                        float z2 = hbuf[128 + r] + p2[f][h] + Hbn[0];
                        float z3 = hbuf[256 + r] + p3[f][h] + Hbp[0];
                        hout[rg]            = 1.0f / (1.0f + expf(-z1));
                        hout[TOTN + rg]     = (z2 > 0.0f) ? (z2 + log1pf(expf(-z2))) : log1pf(expf(z2));
                        hout[2 * TOTN + rg] = 1.0f / (1.0f + expf(-z3));
                    }
            }
            __syncthreads();
        } else {
            #pragma unroll
            for (int f = 0; f < FD; f++) {
                int r0 = row0t + (BIG ? (wm * 32 + f * 16) : (w * 16)) + gid;
                #pragma unroll
                for (int t = 0; t < TD; t++) {
                    int n = (BIG ? wn * 64 : 0) + t * 8 + qid * 2;
                    float2 v0 = make_float2(d[f][t][0], d[f][t][1]);
                    float2 v1 = make_float2(d[f][t][2], d[f][t][3]);
                    if (HASBIAS) {
                        float bx = bias[n], by = bias[n + 1];
                        v0.x += bx; v0.y += by;
                        v1.x += bx; v1.y += by;
                    }
                    if (HASRELU) {
                        v0.x = fmaxf(v0.x, 0.0f); v0.y = fmaxf(v0.y, 0.0f);
                        v1.x = fmaxf(v1.x, 0.0f); v1.y = fmaxf(v1.y, 0.0f);
                    }
                    if (OUTPLANES) {
                        bf16 h0 = __float2bfloat16(v0.x), h1 = __float2bfloat16(v0.y);
                        bf16 h2 = __float2bfloat16(v1.x), h3 = __float2bfloat16(v1.y);
                        *(uint32_t*)&OH[(size_t)r0 * COUT + n] = pack_bf(v0.x, v0.y);
                        *(uint32_t*)&OL[(size_t)r0 * COUT + n] = pack_bf(v0.x - __bfloat162float(h0),
                                                                         v0.y - __bfloat162float(h1));
                        *(uint32_t*)&OH[(size_t)(r0 + 8) * COUT + n] = pack_bf(v1.x, v1.y);
                        *(uint32_t*)&OL[(size_t)(r0 + 8) * COUT + n] = pack_bf(v1.x - __bfloat162float(h2),
                                                                               v1.y - __bfloat162float(h3));
                    } else {
                        *(float2*)&OUT[(size_t)r0 * COUT + n]       = v0;
                        *(float2*)&OUT[(size_t)(r0 + 8) * COUT + n] = v1;
                    }
                }
            }
        }
    };

    if (PIPE) {
        stage_A(blockIdx.x * TILES * 128, 0, 0);
        stage_B_all(0);
        CP_COMMIT();
        for (int t = 0; t < TILES; t++) {
            int row0t = (blockIdx.x * TILES + t) * 128;
            CP_WAIT0();
            __syncthreads();
            if (t + 1 < TILES) {
                stage_A(row0t + 128, 0, (t + 1) & 1);
                CP_COMMIT();
            }
            reset_acc();
            uint32_t aH = sb + (uint32_t)((t & 1) * 2) * ABUFB;
            uint32_t aL = aH + ABUFB;
            #pragma unroll
            for (int s = 0; s < TAPS; s++) mma_chunk(aH, aL, s, ALLTAPS ? s : 0, 0);
            epilogue(row0t);
            __syncthreads();
        }
    } else {
        for (int t = 0; t < TILES; t++) {
            int row0t = (blockIdx.x * TILES + t) * 128;
            reset_acc();
            for (int c = 0; c < NCHC; c++) {
                int c0 = c * KCH;
                __syncthreads();
                stage_A(row0t, c0, 0);
                if (ALLTAPS) stage_B_all(c0);
                else if (TAPS == 1) { if (t == 0) stage_B_all(c0); }
                else stage_B_tap(0, c0, 0);
                CP_COMMIT(); CP_WAIT0();
                __syncthreads();
                #pragma unroll
                for (int s = 0; s < TAPS; s++) {
                    if (BDB && s + 1 < TAPS) {
                        stage_B_tap(s + 1, c0, (s + 1) & 1);
                        CP_COMMIT();
                    }
                    mma_chunk(sb, sb + ABUFB, s, ALLTAPS ? s : 0, BDB ? (s & 1) : 0);
                    if (BDB && s + 1 < TAPS) {
                        CP_WAIT0();
                        __syncthreads();
                    }
                }
            }
            __syncthreads();
            epilogue(row0t);
        }
    }
}

// ---------------- CSR build ----------------
__global__ void count_kernel(const void* edges, int* cnt, int E) {
    int is64 = g_is64;
    int i  = blockIdx.x * blockDim.x + threadIdx.x;
    int st = gridDim.x * blockDim.x;
    int half = E >> 1;
    if (is64) {
        const longlong2* d2 = (const longlong2*)((const long long*)edges + E);
        for (int k = i; k < half; k += st) {
            longlong2 v = d2[k];
            atomicAdd(&cnt[(int)v.x], 1);
            atomicAdd(&cnt[(int)v.y], 1);
        }
        if (i == 0 && (E & 1)) atomicAdd(&cnt[(int)((const long long*)edges)[E + E - 1]], 1);
    } else {
        const int2* d2 = (const int2*)((const int*)edges + E);
        for (int k = i; k < half; k += st) {
            int2 v = d2[k];
            atomicAdd(&cnt[v.x], 1);
            atomicAdd(&cnt[v.y], 1);
        }
        if (i == 0 && (E & 1)) atomicAdd(&cnt[((const int*)edges)[E + E - 1]], 1);
    }
}
__global__ void __launch_bounds__(256)
scan_partial_kernel(const int* __restrict__ cnt, int* part) {
    __shared__ int sh[8];
    int tid = threadIdx.x;
    int v = cnt[blockIdx.x * SCCH + tid];
    #pragma unroll
    for (int o = 16; o > 0; o >>= 1) v += __shfl_xor_sync(0xffffffffu, v, o);
    if ((tid & 31) == 0) sh[tid >> 5] = v;
    __syncthreads();
    if (tid < 8) {
        int s = sh[tid];
        #pragma unroll
        for (int o = 4; o > 0; o >>= 1) s += __shfl_xor_sync(0xffu, s, o, 8);
        if (tid == 0) part[blockIdx.x] = s;
    }
}
__global__ void __launch_bounds__(256)
scan_emit_kernel(const int* __restrict__ cnt, const int* __restrict__ part,
                 int* row_ptr, int* cursor, float* dinv) {
    __shared__ int wsum[8];
    __shared__ int bsum[8];
    int tid  = threadIdx.x;
    int lane = tid & 31;
    int wid  = tid >> 5;

    int bs = 0;
    for (int i = tid; i < blockIdx.x; i += 256) bs += part[i];
    #pragma unroll
    for (int o = 16; o > 0; o >>= 1) bs += __shfl_xor_sync(0xffffffffu, bs, o);
    if (lane == 0) bsum[wid] = bs;
    __syncthreads();
    if (tid == 0) {
        int b = 0;
        #pragma unroll
        for (int k = 0; k < 8; k++) b += bsum[k];
        bsum[0] = b;
    }
    __syncthreads();
    int base = bsum[0];

    int i = blockIdx.x * SCCH + tid;
    int c = cnt[i];
    int v = c;
    #pragma unroll
    for (int o = 1; o < 32; o <<= 1) {
        int u = __shfl_up_sync(0xffffffffu, v, o);
        if (lane >= o) v += u;
    }
    if (lane == 31) wsum[wid] = v;
    __syncthreads();
    if (wid == 0 && lane < 8) {
        int s = wsum[lane];
        #pragma unroll
        for (int o = 1; o < 8; o <<= 1) {
            int u = __shfl_up_sync(0xffu, s, o, 8);
            if (lane >= o) s += u;
        }
        wsum[lane] = s;
    }
    __syncthreads();
    int excl = v - c + (wid > 0 ? wsum[wid - 1] : 0);
    int run = base + excl;
    row_ptr[i] = run;
    cursor[i]  = run;
    dinv[i]    = rsqrtf((float)c + 1.0f);
    if (i == TOTN - 1) row_ptr[TOTN] = run + c;
}
__global__ void fill_kernel(const void* edges, int* cursor, int* adj, int E) {
    int is64 = g_is64;
    int i  = blockIdx.x * blockDim.x + threadIdx.x;
    int st = gridDim.x * blockDim.x;
    int half = E >> 1;
    if (is64) {
        const longlong2* s2 = (const longlong2*)edges;
        const longlong2* d2 = (const longlong2*)((const long long*)edges + E);
        for (int k = i; k < half; k += st) {
            longlong2 sv = s2[k];
            longlong2 dv = d2[k];
            int p0 = atomicAdd(&cursor[(int)dv.x], 1);
            adj[p0] = (int)sv.x;
            int p1 = atomicAdd(&cursor[(int)dv.y], 1);
            adj[p1] = (int)sv.y;
        }
        if (i == 0 && (E & 1)) {
            int s = (int)((const long long*)edges)[E - 1];
            int d = (int)((const long long*)edges)[E + E - 1];
            adj[atomicAdd(&cursor[d], 1)] = s;
        }
    } else {
        const int2* s2 = (const int2*)edges;
        const int2* d2 = (const int2*)((const int*)edges + E);
        for (int k = i; k < half; k += st) {
            int2 sv = s2[k];
            int2 dv = d2[k];
            int p0 = atomicAdd(&cursor[dv.x], 1);
            adj[p0] = sv.x;
            int p1 = atomicAdd(&cursor[dv.y], 1);
            adj[p1] = sv.y;
        }
        if (i == 0 && (E & 1)) {
            int s = ((const int*)edges)[E - 1];
            int d = ((const int*)edges)[E + E - 1];
            adj[atomicAdd(&cursor[d], 1)] = s;
        }
    }
}

// ---------------- CSR gather + fused epilogue ----------------
template <int D, int BIASRELU, int OUTPLANES>
__global__ void gather_kernel(const int* __restrict__ row_ptr, const int* __restrict__ adj,
                              const float* __restrict__ dinv, const float* __restrict__ X,
                              const float* __restrict__ bias, float* __restrict__ OUT,
                              bf16* __restrict__ OH, bf16* __restrict__ OL, int n) {
    int lane = threadIdx.x & 31;
    int node = (blockIdx.x * blockDim.x + threadIdx.x) >> 5;
    if (node >= n) return;
    int beg = row_ptr[node];
    int end = row_ptr[node + 1];
    float di = dinv[node];
    float c  = di * di;
    if (D == 64) {
        float ax = 0.0f, ay = 0.0f;
        #pragma unroll 4
        for (int j = beg; j < end; j++) {
            int s = adj[j];
            float ws = __ldg(&dinv[s]);
            float2 v = ((const float2*)(X + (size_t)s * 64))[lane];
            ax = fmaf(ws, v.x, ax);
            ay = fmaf(ws, v.y, ay);
        }
        float2 xv = ((const float2*)(X + (size_t)node * 64))[lane];
        float2 o;
        o.x = c * (ax + xv.x);
        o.y = c * (ay + xv.y);
        if (BIASRELU) {
            o.x = fmaxf(o.x + bias[2 * lane],     0.0f);
            o.y = fmaxf(o.y + bias[2 * lane + 1], 0.0f);
        }
        if (OUTPLANES) {
            bf16 hx = __float2bfloat16(o.x), hy = __float2bfloat16(o.y);
            *(uint32_t*)&OH[(size_t)node * 64 + 2 * lane] = pack_bf(o.x, o.y);
            *(uint32_t*)&OL[(size_t)node * 64 + 2 * lane] = pack_bf(o.x - __bfloat162float(hx),
                                                                    o.y - __bfloat162float(hy));
        } else {
            ((float2*)(OUT + (size_t)node * 64))[lane] = o;
        }
    } else {
        float acc = 0.0f;
        #pragma unroll 4
        for (int j = beg; j < end; j++) {
            int s = adj[j];
            float ws = __ldg(&dinv[s]);
            acc = fmaf(ws, X[(size_t)s * 32 + lane], acc);
        }
        float v = c * (acc + X[(size_t)node * 32 + lane]);
        if (BIASRELU) v = fmaxf(v + bias[lane], 0.0f);
        if (OUTPLANES) {
            bf16 h = __float2bfloat16(v);
            OH[(size_t)node * 32 + lane] = h;
            OL[(size_t)node * 32 + lane] = __float2bfloat16(v - __bfloat162float(h));
        } else {
            OUT[(size_t)node * 32 + lane] = v;
        }
    }
}

// ---------------- launch ----------------
extern "C" void kernel_launch(void* const* d_in, const int* in_sizes, int n_in,
                              void* d_out, int out_size) {
    const float* x     = (const float*)d_in[0];
    const void*  edges = d_in[1];
    const float* W1  = (const float*)d_in[3];  const float* b1  = (const float*)d_in[4];
    const float* W2  = (const float*)d_in[5];  const float* b2  = (const float*)d_in[6];
    const float* W3  = (const float*)d_in[7];  const float* b3  = (const float*)d_in[8];
    const float* tW1 = (const float*)d_in[9];  const float* tb1 = (const float*)d_in[10];
    const float* tW2 = (const float*)d_in[11]; const float* tb2 = (const float*)d_in[12];
    const float* tW3 = (const float*)d_in[13]; const float* tb3 = (const float*)d_in[14];
    const float* Wpi = (const float*)d_in[15]; const float* bpi = (const float*)d_in[16];
    const float* Wn  = (const float*)d_in[17]; const float* bn  = (const float*)d_in[18];
    const float* Wp  = (const float*)d_in[19]; const float* bp  = (const float*)d_in[20];
    float* out = (float*)d_out;

    const int TOT = in_sizes[0] / FDIM;
    const int E   = in_sizes[1] / 2;

    float *dinv, *H2raw, *H2;
    int *cnt, *rowp, *curs, *adj, *part;
    bf16 *A1h, *A1l, *H1h, *H1l, *A3h, *A3l, *H3h, *H3l, *C1h, *C1l, *C2h, *C2l;
    bf16 *W1h, *W1l, *W2h, *W2l, *W3h, *W3l, *T1h, *T1l, *T2h, *T2l, *T3h, *T3l;
    cudaGetSymbolAddress((void**)&dinv,  g_dinv);
    cudaGetSymbolAddress((void**)&cnt,   g_cnt);
    cudaGetSymbolAddress((void**)&rowp,  g_rowp);
    cudaGetSymbolAddress((void**)&curs,  g_curs);
    cudaGetSymbolAddress((void**)&adj,   g_adj);
    cudaGetSymbolAddress((void**)&part,  g_part);
    cudaGetSymbolAddress((void**)&A1h,   g_A1h);  cudaGetSymbolAddress((void**)&A1l, g_A1l);
    cudaGetSymbolAddress((void**)&H1h,   g_H1h);  cudaGetSymbolAddress((void**)&H1l, g_H1l);
    cudaGetSymbolAddress((void**)&A3h,   g_A3h);  cudaGetSymbolAddress((void**)&A3l, g_A3l);
    cudaGetSymbolAddress((void**)&H3h,   g_H3h);  cudaGetSymbolAddress((void**)&H3l, g_H3l);
    cudaGetSymbolAddress((void**)&C1h,   g_C1h);  cudaGetSymbolAddress((void**)&C1l, g_C1l);
    cudaGetSymbolAddress((void**)&C2h,   g_C2h);  cudaGetSymbolAddress((void**)&C2l, g_C2l);
    cudaGetSymbolAddress((void**)&H2raw, g_H2raw);
    cudaGetSymbolAddress((void**)&H2,    g_H2);
    cudaGetSymbolAddress((void**)&W1h, g_W1h); cudaGetSymbolAddress((void**)&W1l, g_W1l);
    cudaGetSymbolAddress((void**)&W2h, g_W2h); cudaGetSymbolAddress((void**)&W2l, g_W2l);
    cudaGetSymbolAddress((void**)&W3h, g_W3h); cudaGetSymbolAddress((void**)&W3l, g_W3l);
    cudaGetSymbolAddress((void**)&T1h, g_T1h); cudaGetSymbolAddress((void**)&T1l, g_T1l);
    cudaGetSymbolAddress((void**)&T2h, g_T2h); cudaGetSymbolAddress((void**)&T2l, g_T2l);
    cudaGetSymbolAddress((void**)&T3h, g_T3h); cudaGetSymbolAddress((void**)&T3l, g_T3l);

    const int gatherBlocks = (TOT * 32) / 256;
    const int grid1 = TOT / 128;   // TILES=1
    const int grid2 = TOT / 256;   // TILES=2

    // smem sizes (bytes)
    const int SM_G1 = 4 * (128 * 72 * 2)  + 2 * (128 * 72 * 2);              // 110592 (PIPE)
    const int SM_G2 = 2 * (128 * 136 * 2) + 2 * (32 * 136 * 2);              //  87040
    const int SM_G3 = 4 * (128 * 40 * 2)  + 2 * (128 * 40 * 2);              //  61440 (PIPE)
    const int SM_C1 = 2 * (130 * 72 * 2)  + 4 * (128 * 72 * 2);              // 111168 (B dbl-buf)
    const int SM_C2 = 2 * (130 * 72 * 2)  + 2 * (3 * 32 * 72 * 2);           //  65088
    const int SM_C3 = 4 * (130 * 40 * 2)  + 2 * (3 * 128 * 40 * 2) + 1536;   // 104576 (PIPE)

    cudaFuncSetAttribute(mma_layer<64, 128, 1, 64, 1, 1, 1, 0, 2, 1>,  cudaFuncAttributeMaxDynamicSharedMemorySize, SM_G1);
    cudaFuncSetAttribute(mma_layer<128, 32, 1, 128, 0, 0, 0, 0, 2, 0>, cudaFuncAttributeMaxDynamicSharedMemorySize, SM_G2);
    cudaFuncSetAttribute(mma_layer<32, 128, 1, 32, 1, 1, 1, 0, 2, 1>,  cudaFuncAttributeMaxDynamicSharedMemorySize, SM_G3);
    cudaFuncSetAttribute(mma_layer<128, 128, 3, 64, 1, 1, 1, 0, 1, 0>, cudaFuncAttributeMaxDynamicSharedMemorySize, SM_C1);
    cudaFuncSetAttribute(mma_layer<128, 32, 3, 64, 1, 1, 1, 0, 1, 0>,  cudaFuncAttributeMaxDynamicSharedMemorySize, SM_C2);
    cudaFuncSetAttribute(mma_layer<32, 128, 3, 32, 1, 1, 0, 1, 2, 1>,  cudaFuncAttributeMaxDynamicSharedMemorySize, SM_C3);

    // ---- prep + CSR build ----
    prep_kernel<<<256, 256>>>(cnt, TOT, (const unsigned int*)edges, W1, W2, W3, tW1, tW2, tW3);
    count_kernel<<<1024, 256>>>(edges, cnt, E);
    scan_partial_kernel<<<SCB, 256>>>(cnt, part);
    scan_emit_kernel<<<SCB, 256>>>(cnt, part, rowp, curs, dinv);
    fill_kernel<<<1024, 256>>>(edges, curs, adj, E);

    // ---- GCN stack ----
    gather_kernel<64, 0, 1><<<gatherBlocks, 256>>>(rowp, adj, dinv, x, nullptr, nullptr, A1h, A1l, TOT);
    mma_layer<64, 128, 1, 64, 1, 1, 1, 0, 2, 1><<<grid2, 256, SM_G1>>>(
        A1h, A1l, W1h, W1l, b1, nullptr, H1h, H1l,
        nullptr, nullptr, nullptr, nullptr, nullptr, nullptr, nullptr);
    mma_layer<128, 32, 1, 128, 0, 0, 0, 0, 2, 0><<<grid2, 256, SM_G2>>>(
        H1h, H1l, W2h, W2l, nullptr, H2raw, nullptr, nullptr,
        nullptr, nullptr, nullptr, nullptr, nullptr, nullptr, nullptr);
    gather_kernel<32, 1, 0><<<gatherBlocks, 256>>>(rowp, adj, dinv, H2raw, b2, H2, nullptr, nullptr, TOT);
    gather_kernel<32, 0, 1><<<gatherBlocks, 256>>>(rowp, adj, dinv, H2, nullptr, nullptr, A3h, A3l, TOT);
    mma_layer<32, 128, 1, 32, 1, 1, 1, 0, 2, 1><<<grid2, 256, SM_G3>>>(
        A3h, A3l, W3h, W3l, b3, nullptr, H3h, H3l,
        nullptr, nullptr, nullptr, nullptr, nullptr, nullptr, nullptr);

    // ---- temporal conv stack (k=3, pad=1); conv3 fuses the 3 heads ----
    mma_layer<128, 128, 3, 64, 1, 1, 1, 0, 1, 0><<<grid1, 256, SM_C1>>>(
        H3h, H3l, T1h, T1l, tb1, nullptr, C1h, C1l,
        nullptr, nullptr, nullptr, nullptr, nullptr, nullptr, nullptr);
    mma_layer<128, 32, 3, 64, 1, 1, 1, 0, 1, 0><<<grid1, 256, SM_C2>>>(
        C1h, C1l, T2h, T2l, tb2, nullptr, C2h, C2l,
        nullptr, nullptr, nullptr, nullptr, nullptr, nullptr, nullptr);
    mma_layer<32, 128, 3, 32, 1, 1, 0, 1, 2, 1><<<grid2, 256, SM_C3>>>(
        C2h, C2l, T3h, T3l, tb3, nullptr, nullptr, nullptr,
        Wpi, Wn, Wp, bpi, bn, bp, out);
}